// round 3
// baseline (speedup 1.0000x reference)
#include <cuda_runtime.h>
#include <math.h>

#define NTH 512
typedef unsigned long long u64;

// ---------------- scratch globals ----------------
__device__ float g_pstats[128][20];   // per-image [sum(10), sumsq(10)]
__device__ float g_qsel[128][10];     // q gathered at (S1,S2)

// ---------------- f32x2 helpers ----------------
__device__ __forceinline__ void ffma2(u64 &d, u64 a, u64 b) {
    asm("fma.rn.f32x2 %0, %1, %2, %0;" : "+l"(d) : "l"(a), "l"(b));
}
__device__ __forceinline__ u64 fmul2(u64 a, u64 b) {
    u64 d; asm("mul.rn.f32x2 %0, %1, %2;" : "=l"(d) : "l"(a), "l"(b)); return d;
}
__device__ __forceinline__ u64 pk2(float a, float b) {
    u64 r; asm("mov.b64 %0, {%1,%2};" : "=l"(r) : "f"(a), "f"(b)); return r;
}
__device__ __forceinline__ void upk2(u64 v, float &a, float &b) {
    asm("mov.b64 {%0,%1}, %2;" : "=f"(a), "=f"(b) : "l"(v));
}
__device__ __forceinline__ u64 lds64(const float* p) {
    return *reinterpret_cast<const u64*>(p);
}

// ---------------- shared memory layout (floats; all offsets even) ----------------
static constexpr int SZ_XP   = 2 * 68 * 68;
static constexpr int SZ_X1P  = 2 * 36 * 36;
static constexpr int SZ_R1P  = 34 * 34;
static constexpr int SZ_VS   = 34 * 34;
static constexpr int SZ_SA   = 32 * 32;
static constexpr int SZ_BIG  = 66 * 66;
static constexpr int SZ_W5   = 9 * 2 * 25;
static constexpr int SZ_TMP  = 162;
static constexpr int SZ_WQ2  = 16 * 540;   // duplicated-pair conv_q_ws
static constexpr int SZ_WQV2 = 16 * 360;   // duplicated-pair vi_conv_q_ws
static constexpr int SZ_RED  = 16 * 20;

static constexpr int OFF_XP   = 0;
static constexpr int OFF_X1P  = OFF_XP   + SZ_XP;
static constexpr int OFF_R1P  = OFF_X1P  + SZ_X1P;
static constexpr int OFF_VSA  = OFF_R1P  + SZ_R1P;
static constexpr int OFF_VSB  = OFF_VSA  + SZ_VS;
static constexpr int OFF_SA   = OFF_VSB  + SZ_VS;
static constexpr int OFF_MP   = OFF_SA   + SZ_SA;
static constexpr int OFF_RP   = OFF_MP   + SZ_BIG;
static constexpr int OFF_VA   = OFF_RP   + SZ_BIG;
static constexpr int OFF_VB   = OFF_VA   + SZ_BIG;
static constexpr int OFF_W5M  = OFF_VB   + SZ_BIG;
static constexpr int OFF_W5V  = OFF_W5M  + SZ_W5;
static constexpr int OFF_TMPW = OFF_W5V  + SZ_W5;
static constexpr int OFF_WQ2  = OFF_TMPW + SZ_TMP;
static constexpr int OFF_WQV2 = OFF_WQ2  + SZ_WQ2;
static constexpr int OFF_REDU = OFF_WQV2 + SZ_WQV2;
static constexpr int TOTAL_F  = OFF_REDU + SZ_RED;
static constexpr int SMEM_BYTES = TOTAL_F * 4;   // ~198 KB < 227 KB

// ---------------- composed 5x5 boundary-variant builder ----------------
__device__ __forceinline__ float build_w5_entry(const float* tmpw, int e) {
    int v  = e % 5;
    int u  = (e / 5) % 5;
    int ii = (e / 25) % 2;
    int cx = (e / 50) % 3;
    int cy = e / 150;
    float acc = 0.f;
    for (int a = 0; a < 3; ++a) {
        if ((cy == 0 && a == 0) || (cy == 2 && a == 2)) continue;
        for (int b = 0; b < 3; ++b) {
            if ((cx == 0 && b == 0) || (cx == 2 && b == 2)) continue;
            int p = u - a, q = v - b;
            if (p < 0 || p > 2 || q < 0 || q > 2) continue;
            acc += tmpw[((a * 3 + b) * 2 + ii) * 9 + p * 3 + q];
        }
    }
    return acc;
}

// ---------------- packed conv cores ----------------
// Build 9 overlapping pairs {f[t], f[t+1]} from 10 consecutive floats (8B aligned)
__device__ __forceinline__ void mkpairs10(const float* base, u64* pr) {
    u64 e0 = lds64(base), e1 = lds64(base + 2), e2 = lds64(base + 4);
    u64 e3 = lds64(base + 6), e4 = lds64(base + 8);
    float f0, f1, f2, f3, f4, f5, f6, f7, f8, f9;
    upk2(e0, f0, f1); upk2(e1, f2, f3); upk2(e2, f4, f5);
    upk2(e3, f6, f7); upk2(e4, f8, f9);
    pr[0] = e0; pr[2] = e1; pr[4] = e2; pr[6] = e3; pr[8] = e4;
    pr[1] = pk2(f1, f2); pr[3] = pk2(f3, f4); pr[5] = pk2(f5, f6); pr[7] = pk2(f7, f8);
}
// Build 5 overlapping pairs from 6 consecutive floats
__device__ __forceinline__ void mkpairs6(const float* base, u64* pr) {
    u64 e0 = lds64(base), e1 = lds64(base + 2), e2 = lds64(base + 4);
    float f0, f1, f2, f3, f4, f5;
    upk2(e0, f0, f1); upk2(e1, f2, f3); upk2(e2, f4, f5);
    pr[0] = e0; pr[2] = e1; pr[4] = e2;
    pr[1] = pk2(f1, f2); pr[3] = pk2(f3, f4);
}

// Big conv core: 3 inputs (m, r, v), 8 output cols, channels [h*5, h*5+5)
// wbase = Wq2s + k*540; layout per (dy,input): 60 floats, c*6 + dx*2 inside.
__device__ __forceinline__ void big_accum(const float* mB, const float* rB, const float* vBp,
                                          const float* wbase, int h, u64 q[5][4]) {
    #pragma unroll
    for (int input = 0; input < 3; ++input) {
        const float* P = (input == 0) ? mB : (input == 1) ? rB : vBp;
        #pragma unroll
        for (int dy = 0; dy < 3; ++dy) {
            u64 pr[9];
            mkpairs10(P + dy * 66, pr);
            const float* wb = wbase + (dy * 3 + input) * 60 + h * 30;
            #pragma unroll
            for (int cc = 0; cc < 5; ++cc) {
                u64 w0 = lds64(wb + cc * 6);
                u64 w1 = lds64(wb + cc * 6 + 2);
                u64 w2 = lds64(wb + cc * 6 + 4);
                #pragma unroll
                for (int t = 0; t < 4; ++t) {
                    if (input == 0 && dy == 0) q[cc][t] = fmul2(pr[2 * t], w0);
                    else                       ffma2(q[cc][t], pr[2 * t], w0);
                    ffma2(q[cc][t], pr[2 * t + 1], w1);
                    ffma2(q[cc][t], pr[2 * t + 2], w2);
                }
            }
        }
    }
}

// Small conv core: 2 inputs (r1, v), 4 output cols
__device__ __forceinline__ void small_accum(const float* rB, const float* vPp,
                                            const float* wbase, int h, u64 q[5][2]) {
    #pragma unroll
    for (int input = 0; input < 2; ++input) {
        const float* P = (input == 0) ? rB : vPp;
        #pragma unroll
        for (int dy = 0; dy < 3; ++dy) {
            u64 pr[5];
            mkpairs6(P + dy * 34, pr);
            const float* wb = wbase + (dy * 2 + input) * 60 + h * 30;
            #pragma unroll
            for (int cc = 0; cc < 5; ++cc) {
                u64 w0 = lds64(wb + cc * 6);
                u64 w1 = lds64(wb + cc * 6 + 2);
                u64 w2 = lds64(wb + cc * 6 + 4);
                #pragma unroll
                for (int t = 0; t < 2; ++t) {
                    if (input == 0 && dy == 0) q[cc][t] = fmul2(pr[2 * t], w0);
                    else                       ffma2(q[cc][t], pr[2 * t], w0);
                    ffma2(q[cc][t], pr[2 * t + 1], w1);
                    ffma2(q[cc][t], pr[2 * t + 2], w2);
                }
            }
        }
    }
}

__global__ void __launch_bounds__(NTH, 1)
vin_main_kernel(const float* __restrict__ X,
                const int*   __restrict__ S1,
                const int*   __restrict__ S2,
                const float* __restrict__ Wh,
                const float* __restrict__ Wr,
                const float* __restrict__ Wq,
                const float* __restrict__ Whv,
                const float* __restrict__ Wrv,
                const float* __restrict__ Wqv)
{
    extern __shared__ float sm[];
    float* Xp    = sm + OFF_XP;
    float* X1p   = sm + OFF_X1P;
    float* r1p   = sm + OFF_R1P;
    float* vsA   = sm + OFF_VSA;
    float* vsB   = sm + OFF_VSB;
    float* sA    = sm + OFF_SA;
    float* mp    = sm + OFF_MP;
    float* rp    = sm + OFF_RP;
    float* vA    = sm + OFF_VA;
    float* vB    = sm + OFF_VB;
    float* W5m   = sm + OFF_W5M;
    float* W5v   = sm + OFF_W5V;
    float* tmpw  = sm + OFF_TMPW;
    float* Wq2s  = sm + OFF_WQ2;
    float* Wqv2s = sm + OFF_WQV2;
    float* red   = sm + OFF_REDU;

    const int tid = threadIdx.x;
    const int n   = blockIdx.x;

    // P0: zero smem (padding borders + buffers)
    for (int i = tid; i < TOTAL_F; i += NTH) sm[i] = 0.0f;
    __syncthreads();

    // P1: load X padded, stage duplicated-pair weights, vi composed scratch
    const float* Xn = X + (size_t)n * (2 * 64 * 64);
    for (int i = tid; i < 2 * 64 * 64; i += NTH) {
        int ch = i >> 12, y = (i >> 6) & 63, x = i & 63;
        Xp[ch * (68 * 68) + (y + 2) * 68 + (x + 2)] = Xn[i];
    }
    for (int i = tid; i < 4320; i += NTH) {   // Wq (k,c,in,dy,dx)
        int dx = i % 3, dy = (i / 3) % 3, in = (i / 9) % 3, c = (i / 27) % 10, k = i / 270;
        float w = Wq[i];
        int o = k * 540 + (dy * 3 + in) * 60 + c * 6 + dx * 2;
        Wq2s[o] = w; Wq2s[o + 1] = w;
    }
    for (int i = tid; i < 2880; i += NTH) {   // Wqv (k,c,in,dy,dx)
        int dx = i % 3, dy = (i / 3) % 3, in = (i / 9) % 2, c = (i / 18) % 10, k = i / 180;
        float w = Wqv[i];
        int o = k * 360 + (dy * 2 + in) * 60 + c * 6 + dx * 2;
        Wqv2s[o] = w; Wqv2s[o + 1] = w;
    }
    if (tid < 162) {
        int e = tid;
        int q = e % 3, p = (e / 3) % 3, ii = (e / 9) % 2, b = (e / 18) % 3, a = e / 54;
        float acc = 0.f;
        for (int h = 0; h < 150; ++h)
            acc += Wrv[h * 9 + a * 3 + b] * Whv[(h * 2 + ii) * 9 + p * 3 + q];
        tmpw[e] = acc;
    }
    __syncthreads();

    // P2: vi composed variants; maxpool
    if (tid < 450) W5v[tid] = build_w5_entry(tmpw, tid);
    for (int i = tid; i < 2 * 32 * 32; i += NTH) {
        int ch = i >> 10, y = (i >> 5) & 31, x = i & 31;
        const float* b0 = &Xp[ch * (68 * 68) + (2 * y + 2) * 68 + (2 * x + 2)];
        X1p[ch * (36 * 36) + (y + 2) * 36 + (x + 2)] =
            fmaxf(fmaxf(b0[0], b0[1]), fmaxf(b0[68], b0[69]));
    }
    __syncthreads();

    // P3: r1; main composed scratch
    for (int i = tid; i < 32 * 32; i += NTH) {
        int y = i >> 5, x = i & 31;
        int cy = (y == 0) ? 0 : (y == 31) ? 2 : 1;
        int cx = (x == 0) ? 0 : (x == 31) ? 2 : 1;
        const float* w = &W5v[(cy * 3 + cx) * 50];
        float acc = 0.f;
        #pragma unroll
        for (int ii = 0; ii < 2; ++ii)
            #pragma unroll
            for (int u = 0; u < 5; ++u)
                #pragma unroll
                for (int v = 0; v < 5; ++v)
                    acc += w[ii * 25 + u * 5 + v] * X1p[ii * (36 * 36) + (y + u) * 36 + (x + v)];
        r1p[(y + 1) * 34 + (x + 1)] = acc;
    }
    if (tid < 162) {
        int e = tid;
        int q = e % 3, p = (e / 3) % 3, ii = (e / 9) % 2, b = (e / 18) % 3, a = e / 54;
        float acc = 0.f;
        for (int h = 0; h < 150; ++h)
            acc += Wr[h * 9 + a * 3 + b] * Wh[(h * 2 + ii) * 9 + p * 3 + q];
        tmpw[e] = acc;
    }
    __syncthreads();

    // P4: main composed variants
    if (tid < 450) W5m[tid] = build_w5_entry(tmpw, tid);
    __syncthreads();

    // P5: small VI loop (256 threads, 4 cols each, f32x2)
    {
        const int srow = tid >> 3;
        const int sc0  = (tid & 7) * 4;
        float s4[4] = {0.f, 0.f, 0.f, 0.f};
        const float* rB = r1p + srow * 34 + sc0;
        for (int k = 0; k < 16; ++k) {
            if (tid < 256) {
                const float* vcur = (k & 1) ? vsB : vsA;
                float* vnxt = (k & 1) ? vsA : vsB;
                const float* vPp = vcur + srow * 34 + sc0;
                const float* wbase = Wqv2s + k * 360;
                float vm[4] = {-1e30f, -1e30f, -1e30f, -1e30f};
                #pragma unroll
                for (int h = 0; h < 2; ++h) {
                    u64 q[5][2];
                    small_accum(rB, vPp, wbase, h, q);
                    #pragma unroll
                    for (int cc = 0; cc < 5; ++cc) {
                        float a, b;
                        upk2(q[cc][0], a, b); vm[0] = fmaxf(vm[0], a); vm[1] = fmaxf(vm[1], b);
                        upk2(q[cc][1], a, b); vm[2] = fmaxf(vm[2], a); vm[3] = fmaxf(vm[3], b);
                    }
                }
                #pragma unroll
                for (int j = 0; j < 4; ++j) {
                    vnxt[(srow + 1) * 34 + sc0 + 1 + j] = vm[j];
                    s4[j] += vm[j];
                }
            }
            __syncthreads();
        }
        if (tid < 256) {
            #pragma unroll
            for (int j = 0; j < 4; ++j) sA[srow * 32 + sc0 + j] = s4[j];
        }
    }
    __syncthreads();

    // P6: upsample(sA/4) -> mp; composed conv(X) -> rp
    for (int i = tid; i < 64 * 64; i += NTH) {
        int yo = i >> 6, xo = i & 63;
        int jy = yo >> 1, jx = xo >> 1;
        int y0, y1, x0, x1; float wy0, wy1, wx0, wx1;
        if (yo & 1) { y0 = jy; y1 = (jy < 31) ? jy + 1 : 31; wy0 = 0.75f; wy1 = 0.25f; }
        else        { y0 = (jy > 0) ? jy - 1 : 0; y1 = jy;   wy0 = 0.25f; wy1 = 0.75f; }
        if (xo & 1) { x0 = jx; x1 = (jx < 31) ? jx + 1 : 31; wx0 = 0.75f; wx1 = 0.25f; }
        else        { x0 = (jx > 0) ? jx - 1 : 0; x1 = jx;   wx0 = 0.25f; wx1 = 0.75f; }
        float val = wy0 * (wx0 * sA[y0 * 32 + x0] + wx1 * sA[y0 * 32 + x1])
                  + wy1 * (wx0 * sA[y1 * 32 + x0] + wx1 * sA[y1 * 32 + x1]);
        mp[(yo + 1) * 66 + xo + 1] = val * 0.25f;
    }
    for (int i = tid; i < 64 * 64; i += NTH) {
        int y = i >> 6, x = i & 63;
        int cy = (y == 0) ? 0 : (y == 63) ? 2 : 1;
        int cx = (x == 0) ? 0 : (x == 63) ? 2 : 1;
        const float* w = &W5m[(cy * 3 + cx) * 50];
        float acc = 0.f;
        #pragma unroll
        for (int ii = 0; ii < 2; ++ii)
            #pragma unroll
            for (int u = 0; u < 5; ++u)
                #pragma unroll
                for (int v = 0; v < 5; ++v)
                    acc += w[ii * 25 + u * 5 + v] * Xp[ii * (68 * 68) + (y + u) * 68 + (x + v)];
        rp[(y + 1) * 66 + (x + 1)] = acc;
    }
    __syncthreads();

    // P7: big VI loop (512 threads, 8 cols each, f32x2)
    const int brow = tid >> 3;
    const int bc0  = (tid & 7) * 8;
    const float* mB = mp + brow * 66 + bc0;
    const float* rB = rp + brow * 66 + bc0;
    float s8[8];
    #pragma unroll
    for (int j = 0; j < 8; ++j) s8[j] = 0.f;

    for (int k = 0; k < 16; ++k) {
        const float* vcur = (k & 1) ? vB : vA;
        float* vnxt = (k & 1) ? vA : vB;
        const float* vBp = vcur + brow * 66 + bc0;
        const float* wbase = Wq2s + k * 540;
        float vm[8];
        #pragma unroll
        for (int j = 0; j < 8; ++j) vm[j] = -1e30f;
        #pragma unroll
        for (int h = 0; h < 2; ++h) {
            u64 q[5][4];
            big_accum(mB, rB, vBp, wbase, h, q);
            #pragma unroll
            for (int cc = 0; cc < 5; ++cc) {
                float a, b;
                upk2(q[cc][0], a, b); vm[0] = fmaxf(vm[0], a); vm[1] = fmaxf(vm[1], b);
                upk2(q[cc][1], a, b); vm[2] = fmaxf(vm[2], a); vm[3] = fmaxf(vm[3], b);
                upk2(q[cc][2], a, b); vm[4] = fmaxf(vm[4], a); vm[5] = fmaxf(vm[5], b);
                upk2(q[cc][3], a, b); vm[6] = fmaxf(vm[6], a); vm[7] = fmaxf(vm[7], b);
            }
        }
        #pragma unroll
        for (int j = 0; j < 8; ++j) {
            vnxt[(brow + 1) * 66 + bc0 + 1 + j] = vm[j];
            s8[j] += vm[j];
        }
        __syncthreads();
    }

    // v_final = s/16 into vB (borders still zero)
    #pragma unroll
    for (int j = 0; j < 8; ++j)
        vB[(brow + 1) * 66 + bc0 + 1 + j] = s8[j] * 0.0625f;
    __syncthreads();

    // P8: final conv (k=15 weights, v=v_final) + BN stats + gather
    {
        const float* vBp = vB + brow * 66 + bc0;
        const float* wbase = Wq2s + 15 * 540;
        const int s1 = S1[n], s2 = S2[n];
        const bool gat = (brow == s1) && (s2 >= bc0) && (s2 < bc0 + 8);
        const int lane = tid & 31, wrp = tid >> 5;
        #pragma unroll
        for (int h = 0; h < 2; ++h) {
            u64 q[5][4];
            big_accum(mB, rB, vBp, wbase, h, q);
            #pragma unroll
            for (int cc = 0; cc < 5; ++cc) {
                const int c = h * 5 + cc;
                float qa[8];
                upk2(q[cc][0], qa[0], qa[1]);
                upk2(q[cc][1], qa[2], qa[3]);
                upk2(q[cc][2], qa[4], qa[5]);
                upk2(q[cc][3], qa[6], qa[7]);
                float s = 0.f, ss = 0.f;
                #pragma unroll
                for (int j = 0; j < 8; ++j) { s += qa[j]; ss += qa[j] * qa[j]; }
                if (gat) {
                    #pragma unroll
                    for (int j = 0; j < 8; ++j)
                        if (bc0 + j == s2) g_qsel[n][c] = qa[j];
                }
                float v1 = s, v2 = ss;
                #pragma unroll
                for (int off = 16; off > 0; off >>= 1) {
                    v1 += __shfl_down_sync(0xffffffffu, v1, off);
                    v2 += __shfl_down_sync(0xffffffffu, v2, off);
                }
                if (lane == 0) { red[wrp * 20 + c] = v1; red[wrp * 20 + 10 + c] = v2; }
            }
        }
        __syncthreads();
        if (tid < 20) {
            float t = 0.f;
            for (int w = 0; w < 16; ++w) t += red[w * 20 + tid];
            g_pstats[n][tid] = t;
        }
    }
}

__global__ void vin_final_kernel(const float* __restrict__ gamma,
                                 const float* __restrict__ beta,
                                 const float* __restrict__ w1,
                                 const float* __restrict__ w2,
                                 float* __restrict__ out)
{
    __shared__ float part[4][20];
    __shared__ float meanv[10], scalev[10];
    const int t = threadIdx.x;           // 128 threads = image index
    const int lane = t & 31, w = t >> 5;

    #pragma unroll
    for (int s = 0; s < 20; ++s) {
        float x = g_pstats[t][s];
        #pragma unroll
        for (int off = 16; off > 0; off >>= 1)
            x += __shfl_down_sync(0xffffffffu, x, off);
        if (lane == 0) part[w][s] = x;
    }
    __syncthreads();
    if (t < 10) {
        float S = part[0][t] + part[1][t] + part[2][t] + part[3][t];
        float Q = part[0][10 + t] + part[1][10 + t] + part[2][10 + t] + part[3][10 + t];
        float m   = S * (1.0f / 524288.0f);
        float var = Q * (1.0f / 524288.0f) - m * m;
        meanv[t]  = m;
        scalev[t] = rsqrtf(var + 1e-5f);
    }
    __syncthreads();

    float qn[10];
    #pragma unroll
    for (int c = 0; c < 10; ++c)
        qn[c] = (g_qsel[t][c] - meanv[c]) * scalev[c] * gamma[c] + beta[c];
    float a = 0.f;
    #pragma unroll
    for (int c = 0; c < 10; ++c) a += qn[c] * w1[c];
    a = fmaxf(a, 0.f);
    float b[8], bm = 0.f;
    #pragma unroll
    for (int j = 0; j < 8; ++j) {
        float s = 0.f;
        #pragma unroll
        for (int c = 0; c < 10; ++c) s += qn[c] * w2[j * 10 + c];
        b[j] = fmaxf(s, 0.f);
        bm += b[j];
    }
    bm *= 0.125f;
    #pragma unroll
    for (int j = 0; j < 8; ++j) out[t * 8 + j] = a + b[j] - bm;
}

extern "C" void kernel_launch(void* const* d_in, const int* in_sizes, int n_in,
                              void* d_out, int out_size)
{
    const float* X   = (const float*)d_in[0];
    const int*   S1  = (const int*)  d_in[1];
    const int*   S2  = (const int*)  d_in[2];
    const float* Wh  = (const float*)d_in[3];
    const float* Wr  = (const float*)d_in[4];
    const float* Wq  = (const float*)d_in[5];
    const float* gam = (const float*)d_in[6];
    const float* bet = (const float*)d_in[7];
    const float* w1  = (const float*)d_in[8];
    const float* w2  = (const float*)d_in[9];
    const float* Whv = (const float*)d_in[10];
    const float* Wrv = (const float*)d_in[11];
    const float* Wqv = (const float*)d_in[12];
    float* out = (float*)d_out;

    cudaFuncSetAttribute(vin_main_kernel,
                         cudaFuncAttributeMaxDynamicSharedMemorySize, SMEM_BYTES);

    vin_main_kernel<<<128, NTH, SMEM_BYTES>>>(X, S1, S2, Wh, Wr, Wq, Whv, Wrv, Wqv);
    vin_final_kernel<<<1, 128>>>(gam, bet, w1, w2, out);
}

// round 4
// speedup vs baseline: 1.0008x; 1.0008x over previous
#include <cuda_runtime.h>
#include <math.h>

#define NTH 512
typedef unsigned long long u64;

// ---------------- scratch globals ----------------
__device__ float g_pstats[128][20];   // per-image [sum(10), sumsq(10)]
__device__ float g_qsel[128][10];     // q gathered at (S1,S2)

// ---------------- f32x2 helpers ----------------
__device__ __forceinline__ void ffma2(u64 &d, u64 a, u64 b) {
    asm("fma.rn.f32x2 %0, %1, %2, %0;" : "+l"(d) : "l"(a), "l"(b));
}
__device__ __forceinline__ u64 fmul2(u64 a, u64 b) {
    u64 d; asm("mul.rn.f32x2 %0, %1, %2;" : "=l"(d) : "l"(a), "l"(b)); return d;
}
__device__ __forceinline__ u64 pk2(float a, float b) {
    u64 r; asm("mov.b64 %0, {%1,%2};" : "=l"(r) : "f"(a), "f"(b)); return r;
}
__device__ __forceinline__ void upk2(u64 v, float &a, float &b) {
    asm("mov.b64 {%0,%1}, %2;" : "=f"(a), "=f"(b) : "l"(v));
}
__device__ __forceinline__ u64 lds64(const float* p) {
    return *reinterpret_cast<const u64*>(p);
}

// ---------------- shared memory layout (floats; all offsets even) ----------------
static constexpr int SZ_XP   = 2 * 68 * 68;
static constexpr int SZ_X1P  = 2 * 36 * 36;
static constexpr int SZ_R1P  = 34 * 34;
static constexpr int SZ_VS   = 34 * 34;
static constexpr int SZ_SA   = 32 * 32;
static constexpr int SZ_BIG  = 66 * 66;
static constexpr int SZ_W5   = 9 * 2 * 25;
static constexpr int SZ_TMP  = 162;
static constexpr int SZ_WQ2  = 16 * 540;   // duplicated-pair conv_q_ws
static constexpr int SZ_WQV2 = 16 * 360;   // duplicated-pair vi_conv_q_ws
static constexpr int SZ_RED  = 16 * 20;

static constexpr int OFF_XP   = 0;
static constexpr int OFF_X1P  = OFF_XP   + SZ_XP;
static constexpr int OFF_R1P  = OFF_X1P  + SZ_X1P;
static constexpr int OFF_VSA  = OFF_R1P  + SZ_R1P;
static constexpr int OFF_VSB  = OFF_VSA  + SZ_VS;
static constexpr int OFF_SA   = OFF_VSB  + SZ_VS;
static constexpr int OFF_MP   = OFF_SA   + SZ_SA;
static constexpr int OFF_RP   = OFF_MP   + SZ_BIG;
static constexpr int OFF_VA   = OFF_RP   + SZ_BIG;
static constexpr int OFF_VB   = OFF_VA   + SZ_BIG;
static constexpr int OFF_W5M  = OFF_VB   + SZ_BIG;
static constexpr int OFF_W5V  = OFF_W5M  + SZ_W5;
static constexpr int OFF_TMPW = OFF_W5V  + SZ_W5;
static constexpr int OFF_WQ2  = OFF_TMPW + SZ_TMP;
static constexpr int OFF_WQV2 = OFF_WQ2  + SZ_WQ2;
static constexpr int OFF_REDU = OFF_WQV2 + SZ_WQV2;
static constexpr int TOTAL_F  = OFF_REDU + SZ_RED;
static constexpr int SMEM_BYTES = TOTAL_F * 4;   // ~198 KB < 227 KB

// ---------------- composed 5x5 boundary-variant builder ----------------
__device__ __forceinline__ float build_w5_entry(const float* tmpw, int e) {
    int v  = e % 5;
    int u  = (e / 5) % 5;
    int ii = (e / 25) % 2;
    int cx = (e / 50) % 3;
    int cy = e / 150;
    float acc = 0.f;
    for (int a = 0; a < 3; ++a) {
        if ((cy == 0 && a == 0) || (cy == 2 && a == 2)) continue;
        for (int b = 0; b < 3; ++b) {
            if ((cx == 0 && b == 0) || (cx == 2 && b == 2)) continue;
            int p = u - a, q = v - b;
            if (p < 0 || p > 2 || q < 0 || q > 2) continue;
            acc += tmpw[((a * 3 + b) * 2 + ii) * 9 + p * 3 + q];
        }
    }
    return acc;
}

// ---------------- packed conv cores ----------------
// Build 9 overlapping pairs {f[t], f[t+1]} from 10 consecutive floats (8B aligned)
__device__ __forceinline__ void mkpairs10(const float* base, u64* pr) {
    u64 e0 = lds64(base), e1 = lds64(base + 2), e2 = lds64(base + 4);
    u64 e3 = lds64(base + 6), e4 = lds64(base + 8);
    float f0, f1, f2, f3, f4, f5, f6, f7, f8, f9;
    upk2(e0, f0, f1); upk2(e1, f2, f3); upk2(e2, f4, f5);
    upk2(e3, f6, f7); upk2(e4, f8, f9);
    pr[0] = e0; pr[2] = e1; pr[4] = e2; pr[6] = e3; pr[8] = e4;
    pr[1] = pk2(f1, f2); pr[3] = pk2(f3, f4); pr[5] = pk2(f5, f6); pr[7] = pk2(f7, f8);
}
// Build 5 overlapping pairs from 6 consecutive floats
__device__ __forceinline__ void mkpairs6(const float* base, u64* pr) {
    u64 e0 = lds64(base), e1 = lds64(base + 2), e2 = lds64(base + 4);
    float f0, f1, f2, f3, f4, f5;
    upk2(e0, f0, f1); upk2(e1, f2, f3); upk2(e2, f4, f5);
    pr[0] = e0; pr[2] = e1; pr[4] = e2;
    pr[1] = pk2(f1, f2); pr[3] = pk2(f3, f4);
}

// Big conv core: 3 inputs (m, r, v), 8 output cols, channels [h*5, h*5+5)
// wbase = Wq2s + k*540; layout per (dy,input): 60 floats, c*6 + dx*2 inside.
__device__ __forceinline__ void big_accum(const float* mB, const float* rB, const float* vBp,
                                          const float* wbase, int h, u64 q[5][4]) {
    #pragma unroll
    for (int input = 0; input < 3; ++input) {
        const float* P = (input == 0) ? mB : (input == 1) ? rB : vBp;
        #pragma unroll
        for (int dy = 0; dy < 3; ++dy) {
            u64 pr[9];
            mkpairs10(P + dy * 66, pr);
            const float* wb = wbase + (dy * 3 + input) * 60 + h * 30;
            #pragma unroll
            for (int cc = 0; cc < 5; ++cc) {
                u64 w0 = lds64(wb + cc * 6);
                u64 w1 = lds64(wb + cc * 6 + 2);
                u64 w2 = lds64(wb + cc * 6 + 4);
                #pragma unroll
                for (int t = 0; t < 4; ++t) {
                    if (input == 0 && dy == 0) q[cc][t] = fmul2(pr[2 * t], w0);
                    else                       ffma2(q[cc][t], pr[2 * t], w0);
                    ffma2(q[cc][t], pr[2 * t + 1], w1);
                    ffma2(q[cc][t], pr[2 * t + 2], w2);
                }
            }
        }
    }
}

// Small conv core: 2 inputs (r1, v), 4 output cols
__device__ __forceinline__ void small_accum(const float* rB, const float* vPp,
                                            const float* wbase, int h, u64 q[5][2]) {
    #pragma unroll
    for (int input = 0; input < 2; ++input) {
        const float* P = (input == 0) ? rB : vPp;
        #pragma unroll
        for (int dy = 0; dy < 3; ++dy) {
            u64 pr[5];
            mkpairs6(P + dy * 34, pr);
            const float* wb = wbase + (dy * 2 + input) * 60 + h * 30;
            #pragma unroll
            for (int cc = 0; cc < 5; ++cc) {
                u64 w0 = lds64(wb + cc * 6);
                u64 w1 = lds64(wb + cc * 6 + 2);
                u64 w2 = lds64(wb + cc * 6 + 4);
                #pragma unroll
                for (int t = 0; t < 2; ++t) {
                    if (input == 0 && dy == 0) q[cc][t] = fmul2(pr[2 * t], w0);
                    else                       ffma2(q[cc][t], pr[2 * t], w0);
                    ffma2(q[cc][t], pr[2 * t + 1], w1);
                    ffma2(q[cc][t], pr[2 * t + 2], w2);
                }
            }
        }
    }
}

__global__ void __launch_bounds__(NTH, 1)
vin_main_kernel(const float* __restrict__ X,
                const int*   __restrict__ S1,
                const int*   __restrict__ S2,
                const float* __restrict__ Wh,
                const float* __restrict__ Wr,
                const float* __restrict__ Wq,
                const float* __restrict__ Whv,
                const float* __restrict__ Wrv,
                const float* __restrict__ Wqv)
{
    extern __shared__ float sm[];
    float* Xp    = sm + OFF_XP;
    float* X1p   = sm + OFF_X1P;
    float* r1p   = sm + OFF_R1P;
    float* vsA   = sm + OFF_VSA;
    float* vsB   = sm + OFF_VSB;
    float* sA    = sm + OFF_SA;
    float* mp    = sm + OFF_MP;
    float* rp    = sm + OFF_RP;
    float* vA    = sm + OFF_VA;
    float* vB    = sm + OFF_VB;
    float* W5m   = sm + OFF_W5M;
    float* W5v   = sm + OFF_W5V;
    float* tmpw  = sm + OFF_TMPW;
    float* Wq2s  = sm + OFF_WQ2;
    float* Wqv2s = sm + OFF_WQV2;
    float* red   = sm + OFF_REDU;

    const int tid = threadIdx.x;
    const int n   = blockIdx.x;

    // P0: zero smem (padding borders + buffers)
    for (int i = tid; i < TOTAL_F; i += NTH) sm[i] = 0.0f;
    __syncthreads();

    // P1: load X padded, stage duplicated-pair weights, vi composed scratch
    const float* Xn = X + (size_t)n * (2 * 64 * 64);
    for (int i = tid; i < 2 * 64 * 64; i += NTH) {
        int ch = i >> 12, y = (i >> 6) & 63, x = i & 63;
        Xp[ch * (68 * 68) + (y + 2) * 68 + (x + 2)] = Xn[i];
    }
    for (int i = tid; i < 4320; i += NTH) {   // Wq (k,c,in,dy,dx)
        int dx = i % 3, dy = (i / 3) % 3, in = (i / 9) % 3, c = (i / 27) % 10, k = i / 270;
        float w = Wq[i];
        int o = k * 540 + (dy * 3 + in) * 60 + c * 6 + dx * 2;
        Wq2s[o] = w; Wq2s[o + 1] = w;
    }
    for (int i = tid; i < 2880; i += NTH) {   // Wqv (k,c,in,dy,dx)
        int dx = i % 3, dy = (i / 3) % 3, in = (i / 9) % 2, c = (i / 18) % 10, k = i / 180;
        float w = Wqv[i];
        int o = k * 360 + (dy * 2 + in) * 60 + c * 6 + dx * 2;
        Wqv2s[o] = w; Wqv2s[o + 1] = w;
    }
    if (tid < 162) {
        int e = tid;
        int q = e % 3, p = (e / 3) % 3, ii = (e / 9) % 2, b = (e / 18) % 3, a = e / 54;
        float acc = 0.f;
        for (int h = 0; h < 150; ++h)
            acc += Wrv[h * 9 + a * 3 + b] * Whv[(h * 2 + ii) * 9 + p * 3 + q];
        tmpw[e] = acc;
    }
    __syncthreads();

    // P2: vi composed variants; maxpool
    if (tid < 450) W5v[tid] = build_w5_entry(tmpw, tid);
    for (int i = tid; i < 2 * 32 * 32; i += NTH) {
        int ch = i >> 10, y = (i >> 5) & 31, x = i & 31;
        const float* b0 = &Xp[ch * (68 * 68) + (2 * y + 2) * 68 + (2 * x + 2)];
        X1p[ch * (36 * 36) + (y + 2) * 36 + (x + 2)] =
            fmaxf(fmaxf(b0[0], b0[1]), fmaxf(b0[68], b0[69]));
    }
    __syncthreads();

    // P3: r1; main composed scratch
    for (int i = tid; i < 32 * 32; i += NTH) {
        int y = i >> 5, x = i & 31;
        int cy = (y == 0) ? 0 : (y == 31) ? 2 : 1;
        int cx = (x == 0) ? 0 : (x == 31) ? 2 : 1;
        const float* w = &W5v[(cy * 3 + cx) * 50];
        float acc = 0.f;
        #pragma unroll
        for (int ii = 0; ii < 2; ++ii)
            #pragma unroll
            for (int u = 0; u < 5; ++u)
                #pragma unroll
                for (int v = 0; v < 5; ++v)
                    acc += w[ii * 25 + u * 5 + v] * X1p[ii * (36 * 36) + (y + u) * 36 + (x + v)];
        r1p[(y + 1) * 34 + (x + 1)] = acc;
    }
    if (tid < 162) {
        int e = tid;
        int q = e % 3, p = (e / 3) % 3, ii = (e / 9) % 2, b = (e / 18) % 3, a = e / 54;
        float acc = 0.f;
        for (int h = 0; h < 150; ++h)
            acc += Wr[h * 9 + a * 3 + b] * Wh[(h * 2 + ii) * 9 + p * 3 + q];
        tmpw[e] = acc;
    }
    __syncthreads();

    // P4: main composed variants
    if (tid < 450) W5m[tid] = build_w5_entry(tmpw, tid);
    __syncthreads();

    // P5: small VI loop (256 threads, 4 cols each, f32x2)
    {
        const int srow = tid >> 3;
        const int sc0  = (tid & 7) * 4;
        float s4[4] = {0.f, 0.f, 0.f, 0.f};
        const float* rB = r1p + srow * 34 + sc0;
        for (int k = 0; k < 16; ++k) {
            if (tid < 256) {
                const float* vcur = (k & 1) ? vsB : vsA;
                float* vnxt = (k & 1) ? vsA : vsB;
                const float* vPp = vcur + srow * 34 + sc0;
                const float* wbase = Wqv2s + k * 360;
                float vm[4] = {-1e30f, -1e30f, -1e30f, -1e30f};
                #pragma unroll
                for (int h = 0; h < 2; ++h) {
                    u64 q[5][2];
                    small_accum(rB, vPp, wbase, h, q);
                    #pragma unroll
                    for (int cc = 0; cc < 5; ++cc) {
                        float a, b;
                        upk2(q[cc][0], a, b); vm[0] = fmaxf(vm[0], a); vm[1] = fmaxf(vm[1], b);
                        upk2(q[cc][1], a, b); vm[2] = fmaxf(vm[2], a); vm[3] = fmaxf(vm[3], b);
                    }
                }
                #pragma unroll
                for (int j = 0; j < 4; ++j) {
                    vnxt[(srow + 1) * 34 + sc0 + 1 + j] = vm[j];
                    s4[j] += vm[j];
                }
            }
            __syncthreads();
        }
        if (tid < 256) {
            #pragma unroll
            for (int j = 0; j < 4; ++j) sA[srow * 32 + sc0 + j] = s4[j];
        }
    }
    __syncthreads();

    // P6: upsample(sA/4) -> mp; composed conv(X) -> rp
    for (int i = tid; i < 64 * 64; i += NTH) {
        int yo = i >> 6, xo = i & 63;
        int jy = yo >> 1, jx = xo >> 1;
        int y0, y1, x0, x1; float wy0, wy1, wx0, wx1;
        if (yo & 1) { y0 = jy; y1 = (jy < 31) ? jy + 1 : 31; wy0 = 0.75f; wy1 = 0.25f; }
        else        { y0 = (jy > 0) ? jy - 1 : 0; y1 = jy;   wy0 = 0.25f; wy1 = 0.75f; }
        if (xo & 1) { x0 = jx; x1 = (jx < 31) ? jx + 1 : 31; wx0 = 0.75f; wx1 = 0.25f; }
        else        { x0 = (jx > 0) ? jx - 1 : 0; x1 = jx;   wx0 = 0.25f; wx1 = 0.75f; }
        float val = wy0 * (wx0 * sA[y0 * 32 + x0] + wx1 * sA[y0 * 32 + x1])
                  + wy1 * (wx0 * sA[y1 * 32 + x0] + wx1 * sA[y1 * 32 + x1]);
        mp[(yo + 1) * 66 + xo + 1] = val * 0.25f;
    }
    for (int i = tid; i < 64 * 64; i += NTH) {
        int y = i >> 6, x = i & 63;
        int cy = (y == 0) ? 0 : (y == 63) ? 2 : 1;
        int cx = (x == 0) ? 0 : (x == 63) ? 2 : 1;
        const float* w = &W5m[(cy * 3 + cx) * 50];
        float acc = 0.f;
        #pragma unroll
        for (int ii = 0; ii < 2; ++ii)
            #pragma unroll
            for (int u = 0; u < 5; ++u)
                #pragma unroll
                for (int v = 0; v < 5; ++v)
                    acc += w[ii * 25 + u * 5 + v] * Xp[ii * (68 * 68) + (y + u) * 68 + (x + v)];
        rp[(y + 1) * 66 + (x + 1)] = acc;
    }
    __syncthreads();

    // P7: big VI loop (512 threads, 8 cols each, f32x2)
    const int brow = tid >> 3;
    const int bc0  = (tid & 7) * 8;
    const float* mB = mp + brow * 66 + bc0;
    const float* rB = rp + brow * 66 + bc0;
    float s8[8];
    #pragma unroll
    for (int j = 0; j < 8; ++j) s8[j] = 0.f;

    for (int k = 0; k < 16; ++k) {
        const float* vcur = (k & 1) ? vB : vA;
        float* vnxt = (k & 1) ? vA : vB;
        const float* vBp = vcur + brow * 66 + bc0;
        const float* wbase = Wq2s + k * 540;
        float vm[8];
        #pragma unroll
        for (int j = 0; j < 8; ++j) vm[j] = -1e30f;
        #pragma unroll
        for (int h = 0; h < 2; ++h) {
            u64 q[5][4];
            big_accum(mB, rB, vBp, wbase, h, q);
            #pragma unroll
            for (int cc = 0; cc < 5; ++cc) {
                float a, b;
                upk2(q[cc][0], a, b); vm[0] = fmaxf(vm[0], a); vm[1] = fmaxf(vm[1], b);
                upk2(q[cc][1], a, b); vm[2] = fmaxf(vm[2], a); vm[3] = fmaxf(vm[3], b);
                upk2(q[cc][2], a, b); vm[4] = fmaxf(vm[4], a); vm[5] = fmaxf(vm[5], b);
                upk2(q[cc][3], a, b); vm[6] = fmaxf(vm[6], a); vm[7] = fmaxf(vm[7], b);
            }
        }
        #pragma unroll
        for (int j = 0; j < 8; ++j) {
            vnxt[(brow + 1) * 66 + bc0 + 1 + j] = vm[j];
            s8[j] += vm[j];
        }
        __syncthreads();
    }

    // v_final = s/16 into vB (borders still zero)
    #pragma unroll
    for (int j = 0; j < 8; ++j)
        vB[(brow + 1) * 66 + bc0 + 1 + j] = s8[j] * 0.0625f;
    __syncthreads();

    // P8: final conv (k=15 weights, v=v_final) + BN stats + gather
    {
        const float* vBp = vB + brow * 66 + bc0;
        const float* wbase = Wq2s + 15 * 540;
        const int s1 = S1[n], s2 = S2[n];
        const bool gat = (brow == s1) && (s2 >= bc0) && (s2 < bc0 + 8);
        const int lane = tid & 31, wrp = tid >> 5;
        #pragma unroll
        for (int h = 0; h < 2; ++h) {
            u64 q[5][4];
            big_accum(mB, rB, vBp, wbase, h, q);
            #pragma unroll
            for (int cc = 0; cc < 5; ++cc) {
                const int c = h * 5 + cc;
                float qa[8];
                upk2(q[cc][0], qa[0], qa[1]);
                upk2(q[cc][1], qa[2], qa[3]);
                upk2(q[cc][2], qa[4], qa[5]);
                upk2(q[cc][3], qa[6], qa[7]);
                float s = 0.f, ss = 0.f;
                #pragma unroll
                for (int j = 0; j < 8; ++j) { s += qa[j]; ss += qa[j] * qa[j]; }
                if (gat) {
                    #pragma unroll
                    for (int j = 0; j < 8; ++j)
                        if (bc0 + j == s2) g_qsel[n][c] = qa[j];
                }
                float v1 = s, v2 = ss;
                #pragma unroll
                for (int off = 16; off > 0; off >>= 1) {
                    v1 += __shfl_down_sync(0xffffffffu, v1, off);
                    v2 += __shfl_down_sync(0xffffffffu, v2, off);
                }
                if (lane == 0) { red[wrp * 20 + c] = v1; red[wrp * 20 + 10 + c] = v2; }
            }
        }
        __syncthreads();
        if (tid < 20) {
            float t = 0.f;
            for (int w = 0; w < 16; ++w) t += red[w * 20 + tid];
            g_pstats[n][tid] = t;
        }
    }
}

__global__ void vin_final_kernel(const float* __restrict__ gamma,
                                 const float* __restrict__ beta,
                                 const float* __restrict__ w1,
                                 const float* __restrict__ w2,
                                 float* __restrict__ out)
{
    __shared__ float part[4][20];
    __shared__ float meanv[10], scalev[10];
    const int t = threadIdx.x;           // 128 threads = image index
    const int lane = t & 31, w = t >> 5;

    #pragma unroll
    for (int s = 0; s < 20; ++s) {
        float x = g_pstats[t][s];
        #pragma unroll
        for (int off = 16; off > 0; off >>= 1)
            x += __shfl_down_sync(0xffffffffu, x, off);
        if (lane == 0) part[w][s] = x;
    }
    __syncthreads();
    if (t < 10) {
        float S = part[0][t] + part[1][t] + part[2][t] + part[3][t];
        float Q = part[0][10 + t] + part[1][10 + t] + part[2][10 + t] + part[3][10 + t];
        float m   = S * (1.0f / 524288.0f);
        float var = Q * (1.0f / 524288.0f) - m * m;
        meanv[t]  = m;
        scalev[t] = rsqrtf(var + 1e-5f);
    }
    __syncthreads();

    float qn[10];
    #pragma unroll
    for (int c = 0; c < 10; ++c)
        qn[c] = (g_qsel[t][c] - meanv[c]) * scalev[c] * gamma[c] + beta[c];
    float a = 0.f;
    #pragma unroll
    for (int c = 0; c < 10; ++c) a += qn[c] * w1[c];
    a = fmaxf(a, 0.f);
    float b[8], bm = 0.f;
    #pragma unroll
    for (int j = 0; j < 8; ++j) {
        float s = 0.f;
        #pragma unroll
        for (int c = 0; c < 10; ++c) s += qn[c] * w2[j * 10 + c];
        b[j] = fmaxf(s, 0.f);
        bm += b[j];
    }
    bm *= 0.125f;
    #pragma unroll
    for (int j = 0; j < 8; ++j) out[t * 8 + j] = a + b[j] - bm;
}

extern "C" void kernel_launch(void* const* d_in, const int* in_sizes, int n_in,
                              void* d_out, int out_size)
{
    const float* X   = (const float*)d_in[0];
    const int*   S1  = (const int*)  d_in[1];
    const int*   S2  = (const int*)  d_in[2];
    const float* Wh  = (const float*)d_in[3];
    const float* Wr  = (const float*)d_in[4];
    const float* Wq  = (const float*)d_in[5];
    const float* gam = (const float*)d_in[6];
    const float* bet = (const float*)d_in[7];
    const float* w1  = (const float*)d_in[8];
    const float* w2  = (const float*)d_in[9];
    const float* Whv = (const float*)d_in[10];
    const float* Wrv = (const float*)d_in[11];
    const float* Wqv = (const float*)d_in[12];
    float* out = (float*)d_out;

    cudaFuncSetAttribute(vin_main_kernel,
                         cudaFuncAttributeMaxDynamicSharedMemorySize, SMEM_BYTES);

    vin_main_kernel<<<128, NTH, SMEM_BYTES>>>(X, S1, S2, Wh, Wr, Wq, Whv, Wrv, Wqv);
    vin_final_kernel<<<1, 128>>>(gam, bet, w1, w2, out);
}